// round 1
// baseline (speedup 1.0000x reference)
#include <cuda_runtime.h>

#define EPSF 1e-7f
#define ACLIPF (1.0f - 1e-6f)
#define PI_F 3.14159274101257324f

// Scratch for deterministic two-stage reduction (no device allocs allowed).
static __device__ float g_partials[8192];

__device__ __forceinline__ float giou_loss(float cx0, float cy0, float r0,
                                           float cx1, float cy1, float r1) {
    float dx = cx0 - cx1, dy = cy0 - cy1;
    float d2 = dx * dx + dy * dy;
    float d  = sqrtf(fmaxf(d2, EPSF));
    float rmax = fmaxf(r0, r1), rmin = fminf(r0, r1);
    float rdiff = rmax - rmin;
    bool lens = (d < r0 + r1) && (d > rdiff);
    bool contained = d <= rdiff;

    float r0s = r0 * r0, r1s = r1 * r1;
    float cos0 = fminf(fmaxf((d2 + r0s - r1s) / fmaxf(2.0f * d * r0, EPSF), -ACLIPF), ACLIPF);
    float cos1 = fminf(fmaxf((d2 + r1s - r0s) / fmaxf(2.0f * d * r1, EPSF), -ACLIPF), ACLIPF);
    float t = (r0 + r1 - d) * (d + r0 - r1) * (d - r0 + r1) * (d + r0 + r1);
    float t_safe = lens ? fmaxf(t, EPSF) : 1.0f;
    float lens_area = r0s * acosf(cos0) + r1s * acosf(cos1) - 0.5f * sqrtf(t_safe);

    float inter = lens ? lens_area : (contained ? PI_F * rmin * rmin : 0.0f);
    float uni = PI_F * (r0s + r1s) - inter;
    float iou = inter / fmaxf(uni, EPSF);

    float alpha = acosf(fminf(fmaxf(rdiff / d, 0.0f), ACLIPF));
    float h2 = d2 - rdiff * rdiff;
    float h2_safe = contained ? 1.0f : fmaxf(h2, EPSF);
    float hull_open = rmax * rmax * (PI_F - alpha) + rmin * rmin * alpha
                      + (rmax + rmin) * sqrtf(h2_safe);
    float hull = contained ? PI_F * rmax * rmax : hull_open;

    return 1.0f - (iou - (hull - uni) / fmaxf(hull, EPSF));
}

// Each thread handles 4 elements via 3 float4 loads per input (perfectly
// coalesced 128-bit accesses over the [N,3] layout).
__global__ void __launch_bounds__(256) giou_main_kernel(
    const float* __restrict__ x, const float* __restrict__ y,
    int n /* number of circle pairs */) {
    int quad = blockIdx.x * blockDim.x + threadIdx.x;   // index of 4-element group
    int base = quad * 4;                                // first element index
    float acc = 0.0f;

    if (base + 3 < n) {
        const float4* x4 = (const float4*)x;
        const float4* y4 = (const float4*)y;
        float4 xa = x4[quad * 3 + 0];
        float4 xb = x4[quad * 3 + 1];
        float4 xc = x4[quad * 3 + 2];
        float4 ya = y4[quad * 3 + 0];
        float4 yb = y4[quad * 3 + 1];
        float4 yc = y4[quad * 3 + 2];
        // elems: (xa.x,xa.y,xa.z) (xa.w,xb.x,xb.y) (xb.z,xb.w,xc.x) (xc.y,xc.z,xc.w)
        acc += giou_loss(xa.x, xa.y, xa.z, ya.x, ya.y, ya.z);
        acc += giou_loss(xa.w, xb.x, xb.y, ya.w, yb.x, yb.y);
        acc += giou_loss(xb.z, xb.w, xc.x, yb.z, yb.w, yc.x);
        acc += giou_loss(xc.y, xc.z, xc.w, yc.y, yc.z, yc.w);
    } else if (base < n) {
        for (int i = base; i < n; i++) {
            acc += giou_loss(x[3*i], x[3*i+1], x[3*i+2], y[3*i], y[3*i+1], y[3*i+2]);
        }
    }

    // warp reduce
    #pragma unroll
    for (int off = 16; off > 0; off >>= 1)
        acc += __shfl_xor_sync(0xFFFFFFFFu, acc, off);

    __shared__ float warp_sums[8];
    int lane = threadIdx.x & 31;
    int wid  = threadIdx.x >> 5;
    if (lane == 0) warp_sums[wid] = acc;
    __syncthreads();
    if (wid == 0) {
        float v = (lane < 8) ? warp_sums[lane] : 0.0f;
        #pragma unroll
        for (int off = 4; off > 0; off >>= 1)
            v += __shfl_xor_sync(0xFFFFFFFFu, v, off);
        if (lane == 0) g_partials[blockIdx.x] = v;
    }
}

__global__ void __launch_bounds__(1024) giou_final_kernel(float* __restrict__ out,
                                                          int nblocks) {
    float acc = 0.0f;
    for (int i = threadIdx.x; i < nblocks; i += 1024)
        acc += g_partials[i];
    #pragma unroll
    for (int off = 16; off > 0; off >>= 1)
        acc += __shfl_xor_sync(0xFFFFFFFFu, acc, off);

    __shared__ float warp_sums[32];
    int lane = threadIdx.x & 31;
    int wid  = threadIdx.x >> 5;
    if (lane == 0) warp_sums[wid] = acc;
    __syncthreads();
    if (wid == 0) {
        float v = (lane < 32) ? warp_sums[lane] : 0.0f;
        #pragma unroll
        for (int off = 16; off > 0; off >>= 1)
            v += __shfl_xor_sync(0xFFFFFFFFu, v, off);
        if (lane == 0) out[0] = v;
    }
}

extern "C" void kernel_launch(void* const* d_in, const int* in_sizes, int n_in,
                              void* d_out, int out_size) {
    const float* x = (const float*)d_in[0];
    const float* y = (const float*)d_in[1];
    int n = in_sizes[0] / 3;                 // number of circle pairs
    int quads = (n + 3) / 4;                 // 4 elements per thread
    int threads = 256;
    int blocks = (quads + threads - 1) / threads;  // 4096 for N=4194304
    if (blocks > 8192) blocks = 8192;        // g_partials capacity (n fits anyway)

    giou_main_kernel<<<blocks, threads>>>(x, y, n);
    giou_final_kernel<<<1, 1024>>>((float*)d_out, blocks);
}

// round 2
// speedup vs baseline: 1.7251x; 1.7251x over previous
#include <cuda_runtime.h>

#define EPSF 1e-7f
#define ACLIPF (1.0f - 1e-6f)
#define PI_F 3.14159274101257324f

// Scratch for deterministic single-launch reduction (no device allocs allowed).
static __device__ float g_partials[8192];
static __device__ unsigned int g_ticket = 0;   // self-resetting via atomicInc wrap

// fast sqrt for strictly-positive args (all call sites guarded >= EPSF or >= 1e-6)
__device__ __forceinline__ float fsqrt_pos(float x) {
    return x * rsqrtf(x);
}

// acos approximation for x in [0,1): abs err <= ~6.8e-5
__device__ __forceinline__ float facos_pos(float x) {
    float p = fmaf(x, -0.0187293f, 0.0742610f);
    p = fmaf(x, p, -0.2121144f);
    p = fmaf(x, p, 1.5707288f);
    return fsqrt_pos(1.0f - x) * p;   // 1-x >= 1e-6 after clipping
}

// acos for x in (-1,1) (clipped to +/-ACLIPF)
__device__ __forceinline__ float facos(float x) {
    float v = facos_pos(fabsf(x));
    return (x >= 0.0f) ? v : (PI_F - v);
}

__device__ __forceinline__ float giou_loss(float cx0, float cy0, float r0,
                                           float cx1, float cy1, float r1) {
    float dx = cx0 - cx1, dy = cy0 - cy1;
    float d2 = dx * dx + dy * dy;
    float d2c = fmaxf(d2, EPSF);
    float inv_d = rsqrtf(d2c);
    float d = d2c * inv_d;
    float rmax = fmaxf(r0, r1), rmin = fminf(r0, r1);
    float rdiff = rmax - rmin;
    bool lens = (d < r0 + r1) && (d > rdiff);
    bool contained = d <= rdiff;

    float r0s = r0 * r0, r1s = r1 * r1;
    float cos0 = __fdividef(d2 + r0s - r1s, fmaxf(2.0f * d * r0, EPSF));
    float cos1 = __fdividef(d2 + r1s - r0s, fmaxf(2.0f * d * r1, EPSF));
    cos0 = fminf(fmaxf(cos0, -ACLIPF), ACLIPF);
    cos1 = fminf(fmaxf(cos1, -ACLIPF), ACLIPF);
    float t = (r0 + r1 - d) * (d + r0 - r1) * (d - r0 + r1) * (d + r0 + r1);
    float t_safe = lens ? fmaxf(t, EPSF) : 1.0f;
    float lens_area = r0s * facos(cos0) + r1s * facos(cos1) - 0.5f * fsqrt_pos(t_safe);

    float inter = lens ? lens_area : (contained ? PI_F * rmin * rmin : 0.0f);
    float uni = PI_F * (r0s + r1s) - inter;
    float iou = __fdividef(inter, fmaxf(uni, EPSF));

    float alpha = facos_pos(fminf(fmaxf(rdiff * inv_d, 0.0f), ACLIPF));
    float h2 = d2 - rdiff * rdiff;
    float h2_safe = contained ? 1.0f : fmaxf(h2, EPSF);
    float hull_open = rmax * rmax * (PI_F - alpha) + rmin * rmin * alpha
                      + (rmax + rmin) * fsqrt_pos(h2_safe);
    float hull = contained ? PI_F * rmax * rmax : hull_open;

    return 1.0f - (iou - __fdividef(hull - uni, fmaxf(hull, EPSF)));
}

// 4 elements per thread via 3 float4 loads per input (coalesced 128-bit over [N,3]).
// Last block (ticket pattern) folds g_partials -> out[0] in a fixed order.
__global__ void __launch_bounds__(256) giou_fused_kernel(
    const float* __restrict__ x, const float* __restrict__ y,
    float* __restrict__ out, int n) {
    int quad = blockIdx.x * blockDim.x + threadIdx.x;
    int base = quad * 4;
    float acc = 0.0f;

    if (base + 3 < n) {
        const float4* x4 = (const float4*)x;
        const float4* y4 = (const float4*)y;
        float4 xa = x4[quad * 3 + 0];
        float4 xb = x4[quad * 3 + 1];
        float4 xc = x4[quad * 3 + 2];
        float4 ya = y4[quad * 3 + 0];
        float4 yb = y4[quad * 3 + 1];
        float4 yc = y4[quad * 3 + 2];
        acc += giou_loss(xa.x, xa.y, xa.z, ya.x, ya.y, ya.z);
        acc += giou_loss(xa.w, xb.x, xb.y, ya.w, yb.x, yb.y);
        acc += giou_loss(xb.z, xb.w, xc.x, yb.z, yb.w, yc.x);
        acc += giou_loss(xc.y, xc.z, xc.w, yc.y, yc.z, yc.w);
    } else if (base < n) {
        for (int i = base; i < n; i++) {
            acc += giou_loss(x[3*i], x[3*i+1], x[3*i+2], y[3*i], y[3*i+1], y[3*i+2]);
        }
    }

    // block reduce
    #pragma unroll
    for (int off = 16; off > 0; off >>= 1)
        acc += __shfl_xor_sync(0xFFFFFFFFu, acc, off);

    __shared__ float warp_sums[8];
    __shared__ bool amLast;
    int lane = threadIdx.x & 31;
    int wid  = threadIdx.x >> 5;
    if (lane == 0) warp_sums[wid] = acc;
    __syncthreads();
    if (wid == 0) {
        float v = (lane < 8) ? warp_sums[lane] : 0.0f;
        #pragma unroll
        for (int off = 4; off > 0; off >>= 1)
            v += __shfl_xor_sync(0xFFFFFFFFu, v, off);
        if (lane == 0) {
            g_partials[blockIdx.x] = v;
            __threadfence();
            unsigned int t = atomicInc(&g_ticket, gridDim.x - 1); // wraps to 0 on last
            amLast = (t == gridDim.x - 1);
        }
    }
    __syncthreads();

    if (amLast) {
        __threadfence();
        int nblocks = gridDim.x;
        float a2 = 0.0f;
        for (int i = threadIdx.x; i < nblocks; i += 256)
            a2 += g_partials[i];                      // fixed order -> deterministic
        #pragma unroll
        for (int off = 16; off > 0; off >>= 1)
            a2 += __shfl_xor_sync(0xFFFFFFFFu, a2, off);
        __syncthreads();                              // reuse warp_sums safely
        if (lane == 0) warp_sums[wid] = a2;
        __syncthreads();
        if (wid == 0) {
            float v = (lane < 8) ? warp_sums[lane] : 0.0f;
            #pragma unroll
            for (int off = 4; off > 0; off >>= 1)
                v += __shfl_xor_sync(0xFFFFFFFFu, v, off);
            if (lane == 0) out[0] = v;
        }
    }
}

extern "C" void kernel_launch(void* const* d_in, const int* in_sizes, int n_in,
                              void* d_out, int out_size) {
    const float* x = (const float*)d_in[0];
    const float* y = (const float*)d_in[1];
    int n = in_sizes[0] / 3;                 // number of circle pairs
    int quads = (n + 3) / 4;                 // 4 elements per thread
    int threads = 256;
    int blocks = (quads + threads - 1) / threads;  // 4096 for N=4194304
    if (blocks > 8192) blocks = 8192;        // g_partials capacity (N fits anyway)

    giou_fused_kernel<<<blocks, threads>>>(x, y, (float*)d_out, n);
}